// round 1
// baseline (speedup 1.0000x reference)
#include <cuda_runtime.h>
#include <cuda_bf16.h>
#include <math.h>

// Problem constants
#define BB    4
#define SS    2048
#define DD    2048
#define HH    16
#define DHH   128

// ---------------- scratch (static device memory; no allocation) -------------
__device__ float g_qh [(size_t)BB*SS*DD];    // 64 MB
__device__ float g_kh [(size_t)BB*SS*DHH];   //  4 MB
__device__ float g_vh [(size_t)BB*SS*DHH];   //  4 MB
__device__ float g_ctx[(size_t)BB*SS*DD];    // 64 MB

// ============================================================================
// Generic fp32 SGEMM: C[M,N] = A[M,K] @ B[K,N] + bias[N]
// BM=BN=128, BK=16, 256 threads, 8x8 register tile (quadrant layout).
// Requires M%128==0, N%128==0, K%16==0 (true for all our shapes).
// ============================================================================
#define BM 128
#define BN 128
#define BK 16

__global__ __launch_bounds__(256, 2)
void sgemm_bias(const float* __restrict__ A, const float* __restrict__ B,
                const float* __restrict__ bias, float* __restrict__ C,
                int M, int N, int K)
{
    __shared__ float As[BK][BM + 4];   // A tile stored transposed (k-major), pad 4
    __shared__ float Bs[BK][BN];

    const int tid = threadIdx.x;
    const int tx  = tid & 15;
    const int ty  = tid >> 4;
    const int bx  = blockIdx.x * BN;
    const int by  = blockIdx.y * BM;

    const int row0 = ty * 4;          // quadrant rows: row0..+3, row0+64..+3
    const int row1 = 64 + ty * 4;
    const int col0 = tx * 4;
    const int col1 = 64 + tx * 4;

    float acc[8][8];
    #pragma unroll
    for (int i = 0; i < 8; i++)
        #pragma unroll
        for (int j = 0; j < 8; j++) acc[i][j] = 0.f;

    for (int k0 = 0; k0 < K; k0 += BK) {
        // ---- load A tile (128 rows x 16 cols) = 512 float4, 2 per thread ----
        #pragma unroll
        for (int it = 0; it < 2; ++it) {
            int idx = tid + it * 256;
            int r   = idx >> 2;
            int seg = idx & 3;
            float4 a = *(const float4*)(A + (size_t)(by + r) * K + k0 + seg * 4);
            As[seg*4+0][r] = a.x;
            As[seg*4+1][r] = a.y;
            As[seg*4+2][r] = a.z;
            As[seg*4+3][r] = a.w;
        }
        // ---- load B tile (16 rows x 128 cols) = 512 float4, 2 per thread ----
        #pragma unroll
        for (int it = 0; it < 2; ++it) {
            int idx = tid + it * 256;
            int kr  = idx >> 5;
            int c4  = idx & 31;
            *(float4*)(&Bs[kr][c4 * 4]) =
                *(const float4*)(B + (size_t)(k0 + kr) * N + bx + c4 * 4);
        }
        __syncthreads();

        #pragma unroll
        for (int kk = 0; kk < BK; ++kk) {
            float a[8], b[8];
            *(float4*)&a[0] = *(float4*)&As[kk][row0];
            *(float4*)&a[4] = *(float4*)&As[kk][row1];
            *(float4*)&b[0] = *(float4*)&Bs[kk][col0];
            *(float4*)&b[4] = *(float4*)&Bs[kk][col1];
            #pragma unroll
            for (int i = 0; i < 8; i++)
                #pragma unroll
                for (int j = 0; j < 8; j++)
                    acc[i][j] += a[i] * b[j];
        }
        __syncthreads();
    }

    // ---- epilogue: add bias, store ----
    const float4 bia0 = *(const float4*)(bias + bx + col0);
    const float4 bia1 = *(const float4*)(bias + bx + col1);
    #pragma unroll
    for (int i = 0; i < 8; i++) {
        int row = by + ((i < 4) ? (row0 + i) : (row1 + i - 4));
        float4 o0, o1;
        o0.x = acc[i][0] + bia0.x;  o0.y = acc[i][1] + bia0.y;
        o0.z = acc[i][2] + bia0.z;  o0.w = acc[i][3] + bia0.w;
        o1.x = acc[i][4] + bia1.x;  o1.y = acc[i][5] + bia1.y;
        o1.z = acc[i][6] + bia1.z;  o1.w = acc[i][7] + bia1.w;
        *(float4*)(C + (size_t)row * N + bx + col0) = o0;
        *(float4*)(C + (size_t)row * N + bx + col1) = o1;
    }
}

// ============================================================================
// Fused flash attention (fp32, online softmax), MQA: K/V shared across heads.
//   qh : [B, S, D]   (head h occupies cols h*128 .. +127), pre-projected
//   kh : [B, S, 128]
//   vh : [B, S, 128]
//   ctx: [B, S, D]   output (merged heads)
// grid = (S/64, H, B), block = 256.
// Per block: 64 queries x full key sequence in 64-key tiles.
// ============================================================================
#define QT 64
#define KT 64

__global__ __launch_bounds__(256, 1)
void flash_mqa(const float* __restrict__ qh, const float* __restrict__ kh,
               const float* __restrict__ vh, float* __restrict__ ctx)
{
    extern __shared__ float sm[];
    float* Qs  = sm;               // [64][128]
    float* Kt  = Qs  + 64 * 128;   // [128][64] d-major, XOR-swizzled (f4 granularity)
    float* Vs  = Kt  + 128 * 64;   // [64][128]
    float* Psm = Vs  + 64 * 128;   // [64][65]

    const int tid = threadIdx.x;
    const int tx  = tid & 15;
    const int ty  = tid >> 4;
    const int q0  = blockIdx.x * QT;
    const int h   = blockIdx.y;
    const int b   = blockIdx.z;

    const float scale = 0.08838834764831845f;   // 1/sqrt(128)

    // ---- load Q tile, pre-scaled ----
    const float* qbase = qh + ((size_t)b * SS + q0) * DD + h * DHH;
    #pragma unroll
    for (int j = 0; j < 8; j++) {
        int idx = tid + j * 256;          // 2048 float4
        int r   = idx >> 5;
        int d4  = idx & 31;
        float4 qv = *(const float4*)(qbase + (size_t)r * DD + d4 * 4);
        qv.x *= scale; qv.y *= scale; qv.z *= scale; qv.w *= scale;
        *(float4*)(Qs + r * 128 + d4 * 4) = qv;
    }

    float m[4], l[4], acc[4][8];
    #pragma unroll
    for (int i = 0; i < 4; i++) {
        m[i] = -1e30f; l[i] = 0.f;
        #pragma unroll
        for (int j = 0; j < 8; j++) acc[i][j] = 0.f;
    }

    const float* kbase = kh + (size_t)b * SS * DHH;
    const float* vbase = vh + (size_t)b * SS * DHH;

    for (int k0 = 0; k0 < SS; k0 += KT) {
        __syncthreads();   // previous iteration's readers of Kt/Vs are done

        // ---- load K (transposed + swizzled) and V (straight) ----
        #pragma unroll
        for (int j = 0; j < 8; j++) {
            int idx = tid + j * 256;      // 2048 float4 each
            int c   = idx >> 5;           // key row 0..63
            int d4  = idx & 31;           // f4 index along head dim
            float4 kv = *(const float4*)(kbase + (size_t)(k0 + c) * DHH + d4 * 4);
            int cl = c & 3, ch = c >> 2;
            int sw = (ch ^ (d4 & 15)) << 2;   // (d>>2)&15 == d4&15 for d=4*d4+u
            float kvv[4] = {kv.x, kv.y, kv.z, kv.w};
            #pragma unroll
            for (int u = 0; u < 4; u++)
                Kt[(d4 * 4 + u) * 64 + sw + cl] = kvv[u];

            float4 vv = *(const float4*)(vbase + (size_t)(k0 + c) * DHH + d4 * 4);
            *(float4*)(Vs + c * 128 + d4 * 4) = vv;
        }
        __syncthreads();

        // ---- scores: s[4][4] = Q(4 rows) . K(4 cols) over DH=128 ----
        float s[4][4];
        #pragma unroll
        for (int i = 0; i < 4; i++)
            #pragma unroll
            for (int j = 0; j < 4; j++) s[i][j] = 0.f;

        #pragma unroll 4
        for (int kk = 0; kk < DHH; kk++) {
            float4 kf = *(float4*)(Kt + kk * 64 + ((tx ^ ((kk >> 2) & 15)) << 2));
            #pragma unroll
            for (int rr = 0; rr < 4; rr++) {
                float qv = Qs[(ty * 4 + rr) * 128 + kk];
                s[rr][0] += qv * kf.x;
                s[rr][1] += qv * kf.y;
                s[rr][2] += qv * kf.z;
                s[rr][3] += qv * kf.w;
            }
        }

        // ---- online softmax (row reductions across 16 lanes via shfl.xor) ----
        #pragma unroll
        for (int rr = 0; rr < 4; rr++) {
            float rmax = fmaxf(fmaxf(s[rr][0], s[rr][1]), fmaxf(s[rr][2], s[rr][3]));
            #pragma unroll
            for (int o = 8; o >= 1; o >>= 1)
                rmax = fmaxf(rmax, __shfl_xor_sync(0xffffffffu, rmax, o));
            float mnew = fmaxf(m[rr], rmax);
            float p0 = __expf(s[rr][0] - mnew);
            float p1 = __expf(s[rr][1] - mnew);
            float p2 = __expf(s[rr][2] - mnew);
            float p3 = __expf(s[rr][3] - mnew);
            float rsum = p0 + p1 + p2 + p3;
            #pragma unroll
            for (int o = 8; o >= 1; o >>= 1)
                rsum += __shfl_xor_sync(0xffffffffu, rsum, o);
            float corr = __expf(m[rr] - mnew);
            l[rr] = l[rr] * corr + rsum;
            m[rr] = mnew;
            #pragma unroll
            for (int j = 0; j < 8; j++) acc[rr][j] *= corr;
            int r = ty * 4 + rr;
            Psm[r * 65 + tx * 4 + 0] = p0;
            Psm[r * 65 + tx * 4 + 1] = p1;
            Psm[r * 65 + tx * 4 + 2] = p2;
            Psm[r * 65 + tx * 4 + 3] = p3;
        }
        __syncthreads();

        // ---- PV: acc[4 rows][8 cols], cols = tx + 16*j ----
        #pragma unroll 2
        for (int c = 0; c < KT; c++) {
            float p0 = Psm[(ty * 4 + 0) * 65 + c];
            float p1 = Psm[(ty * 4 + 1) * 65 + c];
            float p2 = Psm[(ty * 4 + 2) * 65 + c];
            float p3 = Psm[(ty * 4 + 3) * 65 + c];
            #pragma unroll
            for (int j = 0; j < 8; j++) {
                float vv = Vs[c * 128 + tx + 16 * j];
                acc[0][j] += p0 * vv;
                acc[1][j] += p1 * vv;
                acc[2][j] += p2 * vv;
                acc[3][j] += p3 * vv;
            }
        }
    }

    // ---- finalize: divide by l, store to ctx (merged-head layout) ----
    float* obase = ctx + ((size_t)b * SS + q0) * DD + h * DHH;
    #pragma unroll
    for (int rr = 0; rr < 4; rr++) {
        float inv = 1.0f / l[rr];
        int r = ty * 4 + rr;
        #pragma unroll
        for (int j = 0; j < 8; j++)
            obase[(size_t)r * DD + tx + 16 * j] = acc[rr][j] * inv;
    }
}

// ============================================================================
// launch
// ============================================================================
extern "C" void kernel_launch(void* const* d_in, const int* in_sizes, int n_in,
                              void* d_out, int out_size)
{
    (void)in_sizes; (void)n_in; (void)out_size;
    const float* q  = (const float*)d_in[0];
    const float* k  = (const float*)d_in[1];
    const float* v  = (const float*)d_in[2];
    const float* Wq = (const float*)d_in[3];
    const float* bq = (const float*)d_in[4];
    const float* Wk = (const float*)d_in[5];
    const float* bk = (const float*)d_in[6];
    const float* Wv = (const float*)d_in[7];
    const float* bv = (const float*)d_in[8];
    const float* Wo = (const float*)d_in[9];
    const float* bo = (const float*)d_in[10];
    float* out = (float*)d_out;

    float *qh, *kh, *vh, *ctx;
    cudaGetSymbolAddress((void**)&qh,  g_qh);
    cudaGetSymbolAddress((void**)&kh,  g_kh);
    cudaGetSymbolAddress((void**)&vh,  g_vh);
    cudaGetSymbolAddress((void**)&ctx, g_ctx);

    const int M = BB * SS;   // 8192

    // allow >48KB dynamic smem for the flash kernel (idempotent, host-side)
    static const size_t FLASH_SMEM =
        (64*128 + 128*64 + 64*128 + 64*65) * sizeof(float);   // 114,944 B
    cudaFuncSetAttribute(flash_mqa, cudaFuncAttributeMaxDynamicSharedMemorySize,
                         (int)FLASH_SMEM);

    // 1) Q projection: qh = q @ Wq + bq        [8192,2048]x[2048,2048]
    {
        dim3 grid(DD / BN, M / BM);
        sgemm_bias<<<grid, 256>>>(q, Wq, bq, qh, M, DD, DD);
    }
    // 2) K projection: kh = k @ Wk + bk        [8192,2048]x[2048,128]
    {
        dim3 grid(DHH / BN, M / BM);
        sgemm_bias<<<grid, 256>>>(k, Wk, bk, kh, M, DHH, DD);
    }
    // 3) V projection
    {
        dim3 grid(DHH / BN, M / BM);
        sgemm_bias<<<grid, 256>>>(v, Wv, bv, vh, M, DHH, DD);
    }
    // 4) fused attention -> ctx
    {
        dim3 grid(SS / QT, HH, BB);
        flash_mqa<<<grid, 256, FLASH_SMEM>>>(qh, kh, vh, ctx);
    }
    // 5) output projection: out = ctx @ Wo + bo
    {
        dim3 grid(DD / BN, M / BM);
        sgemm_bias<<<grid, 256>>>(ctx, Wo, bo, out, M, DD, DD);
    }
}

// round 2
// speedup vs baseline: 1.8977x; 1.8977x over previous
#include <cuda_runtime.h>
#include <cuda_bf16.h>
#include <math.h>

// Problem constants
#define BB    4
#define SS    2048
#define DD    2048
#define HH    16
#define DHH   128

// ---------------- scratch (static device memory; no allocation) -------------
__device__ float g_qh [(size_t)BB*SS*DD];    // 64 MB
__device__ float g_kh [(size_t)BB*SS*DHH];   //  4 MB
__device__ float g_vh [(size_t)BB*SS*DHH];   //  4 MB
__device__ float g_ctx[(size_t)BB*SS*DD];    // 64 MB

// ============================================================================
// helpers: bf16 split + mma.sync m16n8k16 (row.col, f32 accum)
// ============================================================================
__device__ __forceinline__ unsigned pk2(__nv_bfloat16 a, __nv_bfloat16 b) {
    // memory order: a = lower halfword (lower k index)
    return ((unsigned)__bfloat16_as_ushort(b) << 16) | (unsigned)__bfloat16_as_ushort(a);
}

// split two fp32 into hi/lo bf16 pairs (packed)
__device__ __forceinline__ void split2(float x, float y, unsigned& hi, unsigned& lo) {
    __nv_bfloat16 hx = __float2bfloat16(x);
    __nv_bfloat16 hy = __float2bfloat16(y);
    float rx = x - __bfloat162float(hx);
    float ry = y - __bfloat162float(hy);
    hi = pk2(hx, hy);
    lo = pk2(__float2bfloat16(rx), __float2bfloat16(ry));
}

__device__ __forceinline__ void mma16816(float (&c)[4], const unsigned (&a)[4],
                                         unsigned b0, unsigned b1) {
    asm volatile(
        "mma.sync.aligned.m16n8k16.row.col.f32.bf16.bf16.f32 "
        "{%0,%1,%2,%3}, {%4,%5,%6,%7}, {%8,%9}, {%0,%1,%2,%3};"
        : "+f"(c[0]), "+f"(c[1]), "+f"(c[2]), "+f"(c[3])
        : "r"(a[0]), "r"(a[1]), "r"(a[2]), "r"(a[3]), "r"(b0), "r"(b1));
}

// ============================================================================
// bf16x3 GEMM: C[M,N] = A[M,K] @ B[K,N] + bias[N]
// BM=BN=128, BK=32, 256 threads (8 warps, 4x2), warp tile 32x64.
// smem: A as [m][k], B as [n][k] (transposed at load), hi+lo each.
// ============================================================================
#define GSA 40   // bf16 stride of [.][k] smem tiles (80B: frag-load conflict-free)

__global__ __launch_bounds__(256, 2)
void gemm_bf16x3(const float* __restrict__ A, const float* __restrict__ Bm,
                 const float* __restrict__ bias, float* __restrict__ C,
                 int M, int N, int K)
{
    __shared__ __align__(16) unsigned short Ah[128 * GSA];
    __shared__ __align__(16) unsigned short Al[128 * GSA];
    __shared__ __align__(16) unsigned short Bh[128 * GSA];
    __shared__ __align__(16) unsigned short Bl[128 * GSA];

    const int tid = threadIdx.x;
    const int w   = tid >> 5;
    const int ln  = tid & 31;
    const int r4  = ln >> 2;       // 0..7
    const int tig = ln & 3;        // 0..3
    const int bx  = blockIdx.x * 128;
    const int by  = blockIdx.y * 128;
    const int m0  = (w & 3) * 32;  // warp row base
    const int n0  = (w >> 2) * 64; // warp col base

    float acc[16][4];
    #pragma unroll
    for (int i = 0; i < 16; i++)
        #pragma unroll
        for (int j = 0; j < 4; j++) acc[i][j] = 0.f;

    const int bn = tid & 127;           // B-transpose: this thread's n column
    const int bkh = (tid >> 7) * 4;     // 0 or 4

    for (int k0 = 0; k0 < K; k0 += 32) {
        // ---- A tile: 128x32 fp32 -> split -> Ah/Al [m][k] ----
        #pragma unroll
        for (int i = 0; i < 4; i++) {
            int idx = tid + i * 256;
            int r = idx >> 3, c4 = idx & 7;
            float4 a = *(const float4*)(A + (size_t)(by + r) * K + k0 + c4 * 4);
            unsigned h0, l0, h1, l1;
            split2(a.x, a.y, h0, l0);
            split2(a.z, a.w, h1, l1);
            *(uint2*)&Ah[r * GSA + c4 * 4] = make_uint2(h0, h1);
            *(uint2*)&Al[r * GSA + c4 * 4] = make_uint2(l0, l1);
        }
        // ---- B tile: 32x128 fp32 -> transpose+split -> Bh/Bl [n][k] ----
        #pragma unroll
        for (int rep = 0; rep < 4; rep++) {
            int kb = bkh + rep * 8;
            const float* bp = Bm + (size_t)(k0 + kb) * N + bx + bn;
            float b0v = bp[0];
            float b1v = bp[(size_t)N];
            float b2v = bp[(size_t)2 * N];
            float b3v = bp[(size_t)3 * N];
            unsigned h0, l0, h1, l1;
            split2(b0v, b1v, h0, l0);
            split2(b2v, b3v, h1, l1);
            *(uint2*)&Bh[bn * GSA + kb] = make_uint2(h0, h1);
            *(uint2*)&Bl[bn * GSA + kb] = make_uint2(l0, l1);
        }
        __syncthreads();

        #pragma unroll
        for (int ks = 0; ks < 2; ks++) {
            const int kk = ks * 16;
            unsigned ah[2][4], al[2][4];
            #pragma unroll
            for (int mt = 0; mt < 2; mt++) {
                int row = m0 + mt * 16 + r4;
                ah[mt][0] = *(const unsigned*)&Ah[row * GSA + kk + tig * 2];
                ah[mt][1] = *(const unsigned*)&Ah[(row + 8) * GSA + kk + tig * 2];
                ah[mt][2] = *(const unsigned*)&Ah[row * GSA + kk + 8 + tig * 2];
                ah[mt][3] = *(const unsigned*)&Ah[(row + 8) * GSA + kk + 8 + tig * 2];
                al[mt][0] = *(const unsigned*)&Al[row * GSA + kk + tig * 2];
                al[mt][1] = *(const unsigned*)&Al[(row + 8) * GSA + kk + tig * 2];
                al[mt][2] = *(const unsigned*)&Al[row * GSA + kk + 8 + tig * 2];
                al[mt][3] = *(const unsigned*)&Al[(row + 8) * GSA + kk + 8 + tig * 2];
            }
            #pragma unroll
            for (int nt = 0; nt < 8; nt++) {
                int col = n0 + nt * 8 + r4;
                unsigned bh0 = *(const unsigned*)&Bh[col * GSA + kk + tig * 2];
                unsigned bh1 = *(const unsigned*)&Bh[col * GSA + kk + 8 + tig * 2];
                unsigned bl0 = *(const unsigned*)&Bl[col * GSA + kk + tig * 2];
                unsigned bl1 = *(const unsigned*)&Bl[col * GSA + kk + 8 + tig * 2];
                #pragma unroll
                for (int mt = 0; mt < 2; mt++) {
                    mma16816(acc[mt * 8 + nt], ah[mt], bh0, bh1);
                    mma16816(acc[mt * 8 + nt], ah[mt], bl0, bl1);
                    mma16816(acc[mt * 8 + nt], al[mt], bh0, bh1);
                }
            }
        }
        __syncthreads();
    }

    // ---- epilogue ----
    #pragma unroll
    for (int nt = 0; nt < 8; nt++) {
        int col = bx + n0 + nt * 8 + tig * 2;
        float bia0 = bias[col], bia1 = bias[col + 1];
        #pragma unroll
        for (int mt = 0; mt < 2; mt++) {
            int row = by + m0 + mt * 16 + r4;
            float2 o0 = make_float2(acc[mt * 8 + nt][0] + bia0, acc[mt * 8 + nt][1] + bia1);
            float2 o1 = make_float2(acc[mt * 8 + nt][2] + bia0, acc[mt * 8 + nt][3] + bia1);
            *(float2*)(C + (size_t)row * N + col) = o0;
            *(float2*)(C + (size_t)(row + 8) * N + col) = o1;
        }
    }
}

// ============================================================================
// Fused flash attention, bf16x3 tensor-core version.
// grid = (S/64, H, B), block = 256 (8 warps).
// Q tile 64 x 128(dh); key tiles of 64. QK^T and PV via mma, softmax fp32.
// ============================================================================
#define SQ 136   // bf16 stride Q/K tiles [.][dh]
#define SV 72    // bf16 stride Vt [dh][key]
#define SSs 68   // f32 stride score tile
#define SP 72    // bf16 stride P [query][key]

// smem byte offsets
#define OFF_QH   0
#define OFF_QL   (OFF_QH + 64*SQ*2)
#define OFF_KH   (OFF_QL + 64*SQ*2)
#define OFF_KL   (OFF_KH + 64*SQ*2)
#define OFF_VH   (OFF_KL + 64*SQ*2)
#define OFF_VL   (OFF_VH + 128*SV*2)
#define OFF_PH   (OFF_VL + 128*SV*2)
#define OFF_PL   (OFF_PH + 64*SP*2)
#define OFF_S    (OFF_PL + 64*SP*2)
#define OFF_CORR (OFF_S  + 64*SSs*4)
#define FLASH_SMEM_BYTES (OFF_CORR + 64*4)

__global__ __launch_bounds__(256, 1)
void flash_mqa_tc(const float* __restrict__ qh, const float* __restrict__ kh,
                  const float* __restrict__ vh, float* __restrict__ ctx)
{
    extern __shared__ __align__(16) char sm[];
    unsigned short* Qh  = (unsigned short*)(sm + OFF_QH);
    unsigned short* Ql  = (unsigned short*)(sm + OFF_QL);
    unsigned short* Kh  = (unsigned short*)(sm + OFF_KH);
    unsigned short* Kl  = (unsigned short*)(sm + OFF_KL);
    unsigned short* Vth = (unsigned short*)(sm + OFF_VH);
    unsigned short* Vtl = (unsigned short*)(sm + OFF_VL);
    unsigned short* Ph  = (unsigned short*)(sm + OFF_PH);
    unsigned short* Pl  = (unsigned short*)(sm + OFF_PL);
    float* Ssm   = (float*)(sm + OFF_S);
    float* scorr = (float*)(sm + OFF_CORR);

    const int tid = threadIdx.x;
    const int w   = tid >> 5;
    const int ln  = tid & 31;
    const int r4  = ln >> 2;
    const int tig = ln & 3;
    const int q0  = blockIdx.x * 64;
    const int h   = blockIdx.y;
    const int b   = blockIdx.z;

    const float scale = 0.08838834764831845f;   // 1/sqrt(128)

    // ---- load Q tile (pre-scaled, split) ----
    const float* qbase = qh + ((size_t)b * SS + q0) * DD + h * DHH;
    #pragma unroll
    for (int i = 0; i < 8; i++) {
        int idx = tid + i * 256;          // 2048 float4
        int r = idx >> 5, c4 = idx & 31;
        float4 qv = *(const float4*)(qbase + (size_t)r * DD + c4 * 4);
        unsigned h0, l0, h1, l1;
        split2(qv.x * scale, qv.y * scale, h0, l0);
        split2(qv.z * scale, qv.w * scale, h1, l1);
        *(uint2*)&Qh[r * SQ + c4 * 4] = make_uint2(h0, h1);
        *(uint2*)&Ql[r * SQ + c4 * 4] = make_uint2(l0, l1);
    }

    // warp tiles
    const int sm0 = (w & 3) * 16;     // score rows
    const int sn0 = (w >> 2) * 32;    // score cols (keys)
    const int oc0 = (w >> 2) * 64;    // O cols (dh)

    // per-thread softmax state (thread owns row tid>>2, 4x redundant)
    const int srow = tid >> 2;
    float mrun = -1e30f, lrun = 0.f;

    float Oacc[8][4];
    #pragma unroll
    for (int i = 0; i < 8; i++)
        #pragma unroll
        for (int j = 0; j < 4; j++) Oacc[i][j] = 0.f;

    const float* kbase = kh + (size_t)b * SS * DHH;
    const float* vbase = vh + (size_t)b * SS * DHH;
    const int vdh = tid & 127;
    const int vkb = (tid >> 7) * 4;

    for (int k0 = 0; k0 < SS; k0 += 64) {
        __syncthreads();   // prior iteration readers of K/V/P done

        // ---- load K tile: [key][dh], split ----
        #pragma unroll
        for (int i = 0; i < 8; i++) {
            int idx = tid + i * 256;
            int r = idx >> 5, c4 = idx & 31;
            float4 kv = *(const float4*)(kbase + (size_t)(k0 + r) * DHH + c4 * 4);
            unsigned h0, l0, h1, l1;
            split2(kv.x, kv.y, h0, l0);
            split2(kv.z, kv.w, h1, l1);
            *(uint2*)&Kh[r * SQ + c4 * 4] = make_uint2(h0, h1);
            *(uint2*)&Kl[r * SQ + c4 * 4] = make_uint2(l0, l1);
        }
        // ---- load V tile transposed: Vt[dh][key], split ----
        #pragma unroll
        for (int rep = 0; rep < 8; rep++) {
            int kb = vkb + rep * 8;
            const float* vp = vbase + (size_t)(k0 + kb) * DHH + vdh;
            float v0 = vp[0];
            float v1 = vp[DHH];
            float v2 = vp[2 * DHH];
            float v3 = vp[3 * DHH];
            unsigned h0, l0, h1, l1;
            split2(v0, v1, h0, l0);
            split2(v2, v3, h1, l1);
            *(uint2*)&Vth[vdh * SV + kb] = make_uint2(h0, h1);
            *(uint2*)&Vtl[vdh * SV + kb] = make_uint2(l0, l1);
        }
        __syncthreads();

        // ---- scores: warp computes 16 x 32 of S ----
        float sacc[4][4];
        #pragma unroll
        for (int i = 0; i < 4; i++)
            #pragma unroll
            for (int j = 0; j < 4; j++) sacc[i][j] = 0.f;

        #pragma unroll
        for (int ks = 0; ks < 8; ks++) {
            const int kk = ks * 16;
            unsigned ah[4], al[4];
            int row = sm0 + r4;
            ah[0] = *(const unsigned*)&Qh[row * SQ + kk + tig * 2];
            ah[1] = *(const unsigned*)&Qh[(row + 8) * SQ + kk + tig * 2];
            ah[2] = *(const unsigned*)&Qh[row * SQ + kk + 8 + tig * 2];
            ah[3] = *(const unsigned*)&Qh[(row + 8) * SQ + kk + 8 + tig * 2];
            al[0] = *(const unsigned*)&Ql[row * SQ + kk + tig * 2];
            al[1] = *(const unsigned*)&Ql[(row + 8) * SQ + kk + tig * 2];
            al[2] = *(const unsigned*)&Ql[row * SQ + kk + 8 + tig * 2];
            al[3] = *(const unsigned*)&Ql[(row + 8) * SQ + kk + 8 + tig * 2];
            #pragma unroll
            for (int nt = 0; nt < 4; nt++) {
                int col = sn0 + nt * 8 + r4;
                unsigned bh0 = *(const unsigned*)&Kh[col * SQ + kk + tig * 2];
                unsigned bh1 = *(const unsigned*)&Kh[col * SQ + kk + 8 + tig * 2];
                unsigned bl0 = *(const unsigned*)&Kl[col * SQ + kk + tig * 2];
                unsigned bl1 = *(const unsigned*)&Kl[col * SQ + kk + 8 + tig * 2];
                mma16816(sacc[nt], ah, bh0, bh1);
                mma16816(sacc[nt], ah, bl0, bl1);
                mma16816(sacc[nt], al, bh0, bh1);
            }
        }
        // store S to smem (fp32)
        #pragma unroll
        for (int nt = 0; nt < 4; nt++) {
            int col = sn0 + nt * 8 + tig * 2;
            *(float2*)&Ssm[(sm0 + r4) * SSs + col]     = make_float2(sacc[nt][0], sacc[nt][1]);
            *(float2*)&Ssm[(sm0 + r4 + 8) * SSs + col] = make_float2(sacc[nt][2], sacc[nt][3]);
        }
        __syncthreads();

        // ---- softmax: thread owns row srow, quarter (tid&3) of 64 cols ----
        {
            const int q = tid & 3;
            float s[16];
            *(float4*)&s[0]  = *(float4*)&Ssm[srow * SSs + q * 16];
            *(float4*)&s[4]  = *(float4*)&Ssm[srow * SSs + q * 16 + 4];
            *(float4*)&s[8]  = *(float4*)&Ssm[srow * SSs + q * 16 + 8];
            *(float4*)&s[12] = *(float4*)&Ssm[srow * SSs + q * 16 + 12];
            float mloc = s[0];
            #pragma unroll
            for (int i = 1; i < 16; i++) mloc = fmaxf(mloc, s[i]);
            mloc = fmaxf(mloc, __shfl_xor_sync(0xffffffffu, mloc, 1));
            mloc = fmaxf(mloc, __shfl_xor_sync(0xffffffffu, mloc, 2));
            float mnew = fmaxf(mrun, mloc);
            float cf   = __expf(mrun - mnew);
            float p[16], sum = 0.f;
            #pragma unroll
            for (int i = 0; i < 16; i++) { p[i] = __expf(s[i] - mnew); sum += p[i]; }
            sum += __shfl_xor_sync(0xffffffffu, sum, 1);
            sum += __shfl_xor_sync(0xffffffffu, sum, 2);
            lrun = lrun * cf + sum;
            mrun = mnew;
            if (q == 0) scorr[srow] = cf;
            // store P split
            #pragma unroll
            for (int i = 0; i < 4; i++) {
                unsigned h0, l0, h1, l1;
                split2(p[i * 4 + 0], p[i * 4 + 1], h0, l0);
                split2(p[i * 4 + 2], p[i * 4 + 3], h1, l1);
                *(uint2*)&Ph[srow * SP + q * 16 + i * 4] = make_uint2(h0, h1);
                *(uint2*)&Pl[srow * SP + q * 16 + i * 4] = make_uint2(l0, l1);
            }
        }
        __syncthreads();

        // ---- rescale O, then PV mma: warp computes 16 rows x 64 dh ----
        {
            float cr0 = scorr[sm0 + r4];
            float cr1 = scorr[sm0 + r4 + 8];
            #pragma unroll
            for (int nt = 0; nt < 8; nt++) {
                Oacc[nt][0] *= cr0; Oacc[nt][1] *= cr0;
                Oacc[nt][2] *= cr1; Oacc[nt][3] *= cr1;
            }
        }
        #pragma unroll
        for (int ks = 0; ks < 4; ks++) {
            const int kk = ks * 16;
            unsigned ah[4], al[4];
            int row = sm0 + r4;
            ah[0] = *(const unsigned*)&Ph[row * SP + kk + tig * 2];
            ah[1] = *(const unsigned*)&Ph[(row + 8) * SP + kk + tig * 2];
            ah[2] = *(const unsigned*)&Ph[row * SP + kk + 8 + tig * 2];
            ah[3] = *(const unsigned*)&Ph[(row + 8) * SP + kk + 8 + tig * 2];
            al[0] = *(const unsigned*)&Pl[row * SP + kk + tig * 2];
            al[1] = *(const unsigned*)&Pl[(row + 8) * SP + kk + tig * 2];
            al[2] = *(const unsigned*)&Pl[row * SP + kk + 8 + tig * 2];
            al[3] = *(const unsigned*)&Pl[(row + 8) * SP + kk + 8 + tig * 2];
            #pragma unroll
            for (int nt = 0; nt < 8; nt++) {
                int col = oc0 + nt * 8 + r4;   // dh row in Vt
                unsigned bh0 = *(const unsigned*)&Vth[col * SV + kk + tig * 2];
                unsigned bh1 = *(const unsigned*)&Vth[col * SV + kk + 8 + tig * 2];
                unsigned bl0 = *(const unsigned*)&Vtl[col * SV + kk + tig * 2];
                unsigned bl1 = *(const unsigned*)&Vtl[col * SV + kk + 8 + tig * 2];
                mma16816(Oacc[nt], ah, bh0, bh1);
                mma16816(Oacc[nt], ah, bl0, bl1);
                mma16816(Oacc[nt], al, bh0, bh1);
            }
        }
    }

    // ---- finalize ----
    __syncthreads();
    if ((tid & 3) == 0) scorr[srow] = 1.0f / lrun;
    __syncthreads();

    float* obase = ctx + ((size_t)b * SS + q0) * DD + h * DHH;
    float linv0 = scorr[sm0 + r4];
    float linv1 = scorr[sm0 + r4 + 8];
    #pragma unroll
    for (int nt = 0; nt < 8; nt++) {
        int col = oc0 + nt * 8 + tig * 2;
        float2 o0 = make_float2(Oacc[nt][0] * linv0, Oacc[nt][1] * linv0);
        float2 o1 = make_float2(Oacc[nt][2] * linv1, Oacc[nt][3] * linv1);
        *(float2*)(obase + (size_t)(sm0 + r4) * DD + col)     = o0;
        *(float2*)(obase + (size_t)(sm0 + r4 + 8) * DD + col) = o1;
    }
}

// ============================================================================
// launch
// ============================================================================
extern "C" void kernel_launch(void* const* d_in, const int* in_sizes, int n_in,
                              void* d_out, int out_size)
{
    (void)in_sizes; (void)n_in; (void)out_size;
    const float* q  = (const float*)d_in[0];
    const float* k  = (const float*)d_in[1];
    const float* v  = (const float*)d_in[2];
    const float* Wq = (const float*)d_in[3];
    const float* bq = (const float*)d_in[4];
    const float* Wk = (const float*)d_in[5];
    const float* bk = (const float*)d_in[6];
    const float* Wv = (const float*)d_in[7];
    const float* bv = (const float*)d_in[8];
    const float* Wo = (const float*)d_in[9];
    const float* bo = (const float*)d_in[10];
    float* out = (float*)d_out;

    float *qh, *kh, *vh, *ctx;
    cudaGetSymbolAddress((void**)&qh,  g_qh);
    cudaGetSymbolAddress((void**)&kh,  g_kh);
    cudaGetSymbolAddress((void**)&vh,  g_vh);
    cudaGetSymbolAddress((void**)&ctx, g_ctx);

    const int M = BB * SS;   // 8192

    cudaFuncSetAttribute(flash_mqa_tc, cudaFuncAttributeMaxDynamicSharedMemorySize,
                         FLASH_SMEM_BYTES);

    // 1) Q projection
    {
        dim3 grid(DD / 128, M / 128);
        gemm_bf16x3<<<grid, 256>>>(q, Wq, bq, qh, M, DD, DD);
    }
    // 2) K projection
    {
        dim3 grid(DHH / 128, M / 128);
        gemm_bf16x3<<<grid, 256>>>(k, Wk, bk, kh, M, DHH, DD);
    }
    // 3) V projection
    {
        dim3 grid(DHH / 128, M / 128);
        gemm_bf16x3<<<grid, 256>>>(v, Wv, bv, vh, M, DHH, DD);
    }
    // 4) fused attention
    {
        dim3 grid(SS / 64, HH, BB);
        flash_mqa_tc<<<grid, 256, FLASH_SMEM_BYTES>>>(qh, kh, vh, ctx);
    }
    // 5) output projection
    {
        dim3 grid(DD / 128, M / 128);
        gemm_bf16x3<<<grid, 256>>>(ctx, Wo, bo, out, M, DD, DD);
    }
}

// round 3
// speedup vs baseline: 2.6184x; 1.3797x over previous
#include <cuda_runtime.h>
#include <cuda_bf16.h>

// Problem constants
#define BB    4
#define SS    2048
#define DD    2048
#define HH    16
#define DHH   128
#define MM    (BB*SS)   // 8192

// ---------------- static device scratch (pre-split bf16 hi/lo) --------------
__device__ __align__(16) __nv_bfloat16 g_q_hi [(size_t)MM*DD],  g_q_lo [(size_t)MM*DD];
__device__ __align__(16) __nv_bfloat16 g_k_hi [(size_t)MM*DD],  g_k_lo [(size_t)MM*DD];
__device__ __align__(16) __nv_bfloat16 g_v_hi [(size_t)MM*DD],  g_v_lo [(size_t)MM*DD];
__device__ __align__(16) __nv_bfloat16 g_Wq_hi[(size_t)DD*DD],  g_Wq_lo[(size_t)DD*DD];
__device__ __align__(16) __nv_bfloat16 g_Wo_hi[(size_t)DD*DD],  g_Wo_lo[(size_t)DD*DD];
__device__ __align__(16) __nv_bfloat16 g_Wk_hi[(size_t)DD*DHH], g_Wk_lo[(size_t)DD*DHH];
__device__ __align__(16) __nv_bfloat16 g_Wv_hi[(size_t)DD*DHH], g_Wv_lo[(size_t)DD*DHH];
__device__ __align__(16) __nv_bfloat16 g_qh_hi[(size_t)MM*DD],  g_qh_lo[(size_t)MM*DD];
__device__ __align__(16) __nv_bfloat16 g_kh_hi[(size_t)MM*DHH], g_kh_lo[(size_t)MM*DHH];
__device__ __align__(16) __nv_bfloat16 g_vh_hi[(size_t)MM*DHH], g_vh_lo[(size_t)MM*DHH];
__device__ __align__(16) __nv_bfloat16 g_ctx_hi[(size_t)MM*DD], g_ctx_lo[(size_t)MM*DD];

// ---------------- helpers ---------------------------------------------------
__device__ __forceinline__ unsigned pk2(__nv_bfloat16 a, __nv_bfloat16 b) {
    return ((unsigned)__bfloat16_as_ushort(b) << 16) | (unsigned)__bfloat16_as_ushort(a);
}
__device__ __forceinline__ void split2(float x, float y, unsigned& hi, unsigned& lo) {
    __nv_bfloat16 hx = __float2bfloat16(x);
    __nv_bfloat16 hy = __float2bfloat16(y);
    float rx = x - __bfloat162float(hx);
    float ry = y - __bfloat162float(hy);
    hi = pk2(hx, hy);
    lo = pk2(__float2bfloat16(rx), __float2bfloat16(ry));
}
__device__ __forceinline__ void mma16816(float (&c)[4], const unsigned (&a)[4],
                                         unsigned b0, unsigned b1) {
    asm volatile(
        "mma.sync.aligned.m16n8k16.row.col.f32.bf16.bf16.f32 "
        "{%0,%1,%2,%3}, {%4,%5,%6,%7}, {%8,%9}, {%0,%1,%2,%3};"
        : "+f"(c[0]), "+f"(c[1]), "+f"(c[2]), "+f"(c[3])
        : "r"(a[0]), "r"(a[1]), "r"(a[2]), "r"(a[3]), "r"(b0), "r"(b1));
}
__device__ __forceinline__ void ldsm4(unsigned (&r)[4], unsigned a) {
    asm volatile("ldmatrix.sync.aligned.m8n8.x4.shared.b16 {%0,%1,%2,%3}, [%4];"
                 : "=r"(r[0]), "=r"(r[1]), "=r"(r[2]), "=r"(r[3]) : "r"(a));
}
__device__ __forceinline__ void ldsm4t(unsigned (&r)[4], unsigned a) {
    asm volatile("ldmatrix.sync.aligned.m8n8.x4.trans.shared.b16 {%0,%1,%2,%3}, [%4];"
                 : "=r"(r[0]), "=r"(r[1]), "=r"(r[2]), "=r"(r[3]) : "r"(a));
}
__device__ __forceinline__ void cpa16(unsigned dst, const void* src) {
    asm volatile("cp.async.cg.shared.global [%0], [%1], 16;\n" :: "r"(dst), "l"(src));
}
__device__ __forceinline__ void cpa_commit() { asm volatile("cp.async.commit_group;\n"); }
__device__ __forceinline__ void cpa_wait0()  { asm volatile("cp.async.wait_group 0;\n"); }

// ---------------- split kernel (fp32 -> bf16 hi/lo) -------------------------
__global__ void split_kernel(const float* __restrict__ x,
                             __nv_bfloat16* __restrict__ hi,
                             __nv_bfloat16* __restrict__ lo, int n)
{
    int i = (blockIdx.x * blockDim.x + threadIdx.x) * 4;
    if (i >= n) return;
    float4 v = *(const float4*)(x + i);
    unsigned h0, l0, h1, l1;
    split2(v.x, v.y, h0, l0);
    split2(v.z, v.w, h1, l1);
    *(uint2*)&hi[i] = make_uint2(h0, h1);
    *(uint2*)&lo[i] = make_uint2(l0, l1);
}

// ============================================================================
// bf16x3 GEMM with cp.async double buffering.
// C[M,N] = (Ah+Al)[M,K] @ (Bh+Bl)[K,N] + bias (3-term product, lo*lo dropped)
// BM=BN=128, BK=64, 256 threads (8 warps 4x2, warp tile 32x64), 2 stages.
// A smem [m][k] stride 72 bf16; B smem [k][n] stride 136 bf16.
// ============================================================================
#define GSA 72
#define GSB 136
#define GEMM_STAGE 71680          // 2*128*GSA*2 + 2*64*GSB*2
#define GEMM_SMEM  (2*GEMM_STAGE) // 143360

struct GemmArgs {
    const __nv_bfloat16 *a_hi, *a_lo, *b_hi, *b_lo;
    const float* bias;
    float* c;                      // fp32 out (SPLIT_OUT=false)
    __nv_bfloat16 *c_hi, *c_lo;    // split out (SPLIT_OUT=true)
    float scale;
};

template<bool SPLIT_OUT>
__global__ __launch_bounds__(256, 1)
void gemm_tc(GemmArgs ga0, GemmArgs ga1, int M, int N, int K)
{
    GemmArgs g = (blockIdx.z == 0) ? ga0 : ga1;
    extern __shared__ char smem[];
    unsigned sbase = (unsigned)__cvta_generic_to_shared(smem);

    const int tid = threadIdx.x;
    const int w   = tid >> 5;
    const int ln  = tid & 31;
    const int bx  = blockIdx.x * 128;
    const int by  = blockIdx.y * 128;
    const int m0  = (w & 3) * 32;
    const int n0  = (w >> 2) * 64;

    float acc[16][4];
    #pragma unroll
    for (int i = 0; i < 16; i++)
        #pragma unroll
        for (int j = 0; j < 4; j++) acc[i][j] = 0.f;

    auto load_stage = [&](int s, int k0) {
        unsigned st = sbase + s * GEMM_STAGE;
        #pragma unroll
        for (int i = 0; i < 4; i++) {          // A: 128 rows x 64 bf16 (8 chunks)
            int idx = tid + i * 256;
            int r = idx >> 3, c = idx & 7;
            size_t go = (size_t)(by + r) * K + k0 + c * 8;
            unsigned so = (r * GSA + c * 8) * 2;
            cpa16(st + so,         g.a_hi + go);
            cpa16(st + 18432 + so, g.a_lo + go);
        }
        #pragma unroll
        for (int i = 0; i < 4; i++) {          // B: 64 rows x 128 bf16 (16 chunks)
            int idx = tid + i * 256;
            int r = idx >> 4, c = idx & 15;
            size_t go = (size_t)(k0 + r) * N + bx + c * 8;
            unsigned so = (r * GSB + c * 8) * 2;
            cpa16(st + 36864 + so, g.b_hi + go);
            cpa16(st + 54272 + so, g.b_lo + go);
        }
        cpa_commit();
    };

    load_stage(0, 0);
    const int NT = K / 64;
    for (int kt = 0; kt < NT; kt++) {
        cpa_wait0();
        __syncthreads();
        if (kt + 1 < NT) load_stage((kt + 1) & 1, (kt + 1) * 64);

        unsigned st  = sbase + (kt & 1) * GEMM_STAGE;
        unsigned sAh = st, sAl = st + 18432, sBh = st + 36864, sBl = st + 54272;

        #pragma unroll
        for (int ks = 0; ks < 4; ks++) {
            int kk = ks * 16;
            unsigned ah[2][4], al[2][4];
            #pragma unroll
            for (int mt = 0; mt < 2; mt++) {
                unsigned ra = ((m0 + mt * 16 + (ln & 15)) * GSA + kk + (ln >> 4) * 8) * 2;
                ldsm4(ah[mt], sAh + ra);
                ldsm4(al[mt], sAl + ra);
            }
            #pragma unroll
            for (int np = 0; np < 4; np++) {
                unsigned rb = ((kk + (ln & 15)) * GSB + n0 + np * 16 + (ln >> 4) * 8) * 2;
                unsigned bh[4], bl[4];
                ldsm4t(bh, sBh + rb);
                ldsm4t(bl, sBl + rb);
                #pragma unroll
                for (int half = 0; half < 2; half++) {
                    int nt = np * 2 + half;
                    #pragma unroll
                    for (int mt = 0; mt < 2; mt++) {
                        mma16816(acc[mt * 8 + nt], ah[mt], bh[half * 2], bh[half * 2 + 1]);
                        mma16816(acc[mt * 8 + nt], ah[mt], bl[half * 2], bl[half * 2 + 1]);
                        mma16816(acc[mt * 8 + nt], al[mt], bh[half * 2], bh[half * 2 + 1]);
                    }
                }
            }
        }
    }

    // ---- epilogue ----
    const int r4 = ln >> 2, tig = ln & 3;
    #pragma unroll
    for (int nt = 0; nt < 8; nt++) {
        int col = bx + n0 + nt * 8 + tig * 2;
        float b0 = g.bias[col], b1 = g.bias[col + 1];
        #pragma unroll
        for (int mt = 0; mt < 2; mt++) {
            int row = by + m0 + mt * 16 + r4;
            float v00 = (acc[mt * 8 + nt][0] + b0) * g.scale;
            float v01 = (acc[mt * 8 + nt][1] + b1) * g.scale;
            float v10 = (acc[mt * 8 + nt][2] + b0) * g.scale;
            float v11 = (acc[mt * 8 + nt][3] + b1) * g.scale;
            if (SPLIT_OUT) {
                unsigned h, l;
                split2(v00, v01, h, l);
                *(unsigned*)&g.c_hi[(size_t)row * N + col] = h;
                *(unsigned*)&g.c_lo[(size_t)row * N + col] = l;
                split2(v10, v11, h, l);
                *(unsigned*)&g.c_hi[(size_t)(row + 8) * N + col] = h;
                *(unsigned*)&g.c_lo[(size_t)(row + 8) * N + col] = l;
            } else {
                *(float2*)&g.c[(size_t)row * N + col]       = make_float2(v00, v01);
                *(float2*)&g.c[(size_t)(row + 8) * N + col] = make_float2(v10, v11);
            }
        }
    }
}

// ============================================================================
// Fused flash attention, bf16x3, cp.async double-buffered K/V, ldmatrix frags.
// grid=(32,16,4), block=512 (16 warps). Q tile 64x128, key tiles of 64.
// Warp layout: scores (w&3)->16 q rows, (w>>2)->16 keys; PV (w>>2)->32 dh.
// ============================================================================
#define FSQ 136   // bf16 stride for Q/K/V tiles (128 dh + pad)
#define FSP 72    // bf16 stride for P tile (64 keys + pad)
#define FSS 68    // f32 stride for S tile

#define OQH 0
#define OQL 17408
#define OKH 34816     // 2 stages x 17408
#define OKL 69632
#define OVH 104448
#define OVL 139264
#define OPH 174080
#define OPL 183296
#define OS  192512
#define OCR 209920
#define FLASH_SMEM 210176

__global__ __launch_bounds__(512, 1)
void flash_tc(const __nv_bfloat16* __restrict__ qh_hi, const __nv_bfloat16* __restrict__ qh_lo,
              const __nv_bfloat16* __restrict__ kh_hi, const __nv_bfloat16* __restrict__ kh_lo,
              const __nv_bfloat16* __restrict__ vh_hi, const __nv_bfloat16* __restrict__ vh_lo,
              __nv_bfloat16* __restrict__ ctx_hi,      __nv_bfloat16* __restrict__ ctx_lo)
{
    extern __shared__ char smem[];
    unsigned sb = (unsigned)__cvta_generic_to_shared(smem);
    float* corr = (float*)(smem + OCR);
    float* Ssm  = (float*)(smem + OS);

    const int tid = threadIdx.x;
    const int w   = tid >> 5;
    const int ln  = tid & 31;
    const int r4  = ln >> 2;
    const int tig = ln & 3;
    const int q0  = blockIdx.x * 64;
    const int h   = blockIdx.y;
    const int b   = blockIdx.z;
    const int qw  = (w & 3) * 16;     // warp q base
    const int kw  = (w >> 2) * 16;    // warp key base (scores)
    const int dw  = (w >> 2) * 32;    // warp dh base (PV)

    const __nv_bfloat16* qhh = qh_hi + ((size_t)(b * SS + q0)) * DD + h * DHH;
    const __nv_bfloat16* qhl = qh_lo + ((size_t)(b * SS + q0)) * DD + h * DHH;
    const __nv_bfloat16* khh = kh_hi + (size_t)b * SS * DHH;
    const __nv_bfloat16* khl = kh_lo + (size_t)b * SS * DHH;
    const __nv_bfloat16* vhh = vh_hi + (size_t)b * SS * DHH;
    const __nv_bfloat16* vhl = vh_lo + (size_t)b * SS * DHH;

    auto load_kv = [&](int s, int k0) {
        #pragma unroll
        for (int i = 0; i < 2; i++) {
            int idx = tid + i * 512;
            int r = idx >> 4, c = idx & 15;
            size_t go = (size_t)(k0 + r) * DHH + c * 8;
            unsigned so = (r * FSQ + c * 8) * 2 + s * 17408;
            cpa16(sb + OKH + so, khh + go);
            cpa16(sb + OKL + so, khl + go);
            cpa16(sb + OVH + so, vhh + go);
            cpa16(sb + OVL + so, vhl + go);
        }
    };

    // prologue: Q tile + KV stage0 (one group)
    #pragma unroll
    for (int i = 0; i < 2; i++) {
        int idx = tid + i * 512;
        int r = idx >> 4, c = idx & 15;
        unsigned so = (r * FSQ + c * 8) * 2;
        cpa16(sb + OQH + so, qhh + (size_t)r * DD + c * 8);
        cpa16(sb + OQL + so, qhl + (size_t)r * DD + c * 8);
    }
    load_kv(0, 0);
    cpa_commit();

    const int srow = tid >> 3, q8 = tid & 7;
    float mrun = -1e30f, lrun = 0.f;
    float Oacc[4][4];
    #pragma unroll
    for (int i = 0; i < 4; i++)
        #pragma unroll
        for (int j = 0; j < 4; j++) Oacc[i][j] = 0.f;

    for (int it = 0; it < 32; it++) {
        cpa_wait0();
        __syncthreads();
        if (it + 1 < 32) { load_kv((it + 1) & 1, (it + 1) * 64); cpa_commit(); }

        unsigned sKh = sb + OKH + (it & 1) * 17408;
        unsigned sKl = sb + OKL + (it & 1) * 17408;
        unsigned sVh = sb + OVH + (it & 1) * 17408;
        unsigned sVl = sb + OVL + (it & 1) * 17408;

        // ---- scores: warp computes 16q x 16k ----
        float sacc[2][4];
        #pragma unroll
        for (int i = 0; i < 2; i++)
            #pragma unroll
            for (int j = 0; j < 4; j++) sacc[i][j] = 0.f;

        #pragma unroll
        for (int ks = 0; ks < 8; ks++) {
            int kk = ks * 16;
            unsigned aqh[4], aql[4];
            unsigned ra = ((qw + (ln & 15)) * FSQ + kk + (ln >> 4) * 8) * 2;
            ldsm4(aqh, sb + OQH + ra);
            ldsm4(aql, sb + OQL + ra);
            // B frag from K [key][dh] = [n][k]: non-trans, n-rows / k-col-halves
            unsigned rb = ((kw + (ln & 7) + ((ln >> 4) << 3)) * FSQ + kk + ((ln >> 3) & 1) * 8) * 2;
            unsigned bkh[4], bkl[4];
            ldsm4(bkh, sKh + rb);
            ldsm4(bkl, sKl + rb);
            #pragma unroll
            for (int ntile = 0; ntile < 2; ntile++) {
                mma16816(sacc[ntile], aqh, bkh[ntile * 2], bkh[ntile * 2 + 1]);
                mma16816(sacc[ntile], aqh, bkl[ntile * 2], bkl[ntile * 2 + 1]);
                mma16816(sacc[ntile], aql, bkh[ntile * 2], bkh[ntile * 2 + 1]);
            }
        }
        // store S (fp32)
        #pragma unroll
        for (int ntile = 0; ntile < 2; ntile++) {
            int col = kw + ntile * 8 + tig * 2;
            *(float2*)&Ssm[(qw + r4) * FSS + col]     = make_float2(sacc[ntile][0], sacc[ntile][1]);
            *(float2*)&Ssm[(qw + r4 + 8) * FSS + col] = make_float2(sacc[ntile][2], sacc[ntile][3]);
        }
        __syncthreads();

        // ---- softmax: thread owns row srow, 8 cols at q8*8 ----
        {
            float s[8];
            float* Srow = Ssm + srow * FSS + q8 * 8;
            *(float4*)&s[0] = *(float4*)Srow;
            *(float4*)&s[4] = *(float4*)(Srow + 4);
            float mloc = s[0];
            #pragma unroll
            for (int i = 1; i < 8; i++) mloc = fmaxf(mloc, s[i]);
            mloc = fmaxf(mloc, __shfl_xor_sync(0xffffffffu, mloc, 1));
            mloc = fmaxf(mloc, __shfl_xor_sync(0xffffffffu, mloc, 2));
            mloc = fmaxf(mloc, __shfl_xor_sync(0xffffffffu, mloc, 4));
            float mnew = fmaxf(mrun, mloc);
            float p[8], sum = 0.f;
            #pragma unroll
            for (int i = 0; i < 8; i++) { p[i] = __expf(s[i] - mnew); sum += p[i]; }
            sum += __shfl_xor_sync(0xffffffffu, sum, 1);
            sum += __shfl_xor_sync(0xffffffffu, sum, 2);
            sum += __shfl_xor_sync(0xffffffffu, sum, 4);
            float cf = __expf(mrun - mnew);
            lrun = lrun * cf + sum;
            mrun = mnew;
            if (q8 == 0) corr[srow] = cf;
            unsigned short* Ph = (unsigned short*)(smem + OPH);
            unsigned short* Pl = (unsigned short*)(smem + OPL);
            #pragma unroll
            for (int i = 0; i < 4; i++) {
                unsigned hh, ll;
                split2(p[2 * i], p[2 * i + 1], hh, ll);
                *(unsigned*)&Ph[srow * FSP + q8 * 8 + 2 * i] = hh;
                *(unsigned*)&Pl[srow * FSP + q8 * 8 + 2 * i] = ll;
            }
        }
        __syncthreads();

        // ---- rescale O, then PV: warp computes 16q x 32dh ----
        {
            float cr0 = corr[qw + r4];
            float cr1 = corr[qw + r4 + 8];
            #pragma unroll
            for (int nt = 0; nt < 4; nt++) {
                Oacc[nt][0] *= cr0; Oacc[nt][1] *= cr0;
                Oacc[nt][2] *= cr1; Oacc[nt][3] *= cr1;
            }
        }
        #pragma unroll
        for (int ks = 0; ks < 4; ks++) {
            int kk = ks * 16;
            unsigned aph[4], apl[4];
            unsigned ra = ((qw + (ln & 15)) * FSP + kk + (ln >> 4) * 8) * 2;
            ldsm4(aph, sb + OPH + ra);
            ldsm4(apl, sb + OPL + ra);
            #pragma unroll
            for (int np = 0; np < 2; np++) {
                unsigned rb = ((kk + (ln & 15)) * FSQ + dw + np * 16 + (ln >> 4) * 8) * 2;
                unsigned bvh[4], bvl[4];
                ldsm4t(bvh, sVh + rb);
                ldsm4t(bvl, sVl + rb);
                #pragma unroll
                for (int half = 0; half < 2; half++) {
                    int nt = np * 2 + half;
                    mma16816(Oacc[nt], aph, bvh[half * 2], bvh[half * 2 + 1]);
                    mma16816(Oacc[nt], aph, bvl[half * 2], bvl[half * 2 + 1]);
                    mma16816(Oacc[nt], apl, bvh[half * 2], bvh[half * 2 + 1]);
                }
            }
        }
    }

    // ---- finalize: 1/l, write split ctx ----
    __syncthreads();
    if (q8 == 0) corr[srow] = 1.0f / lrun;
    __syncthreads();
    float li0 = corr[qw + r4];
    float li1 = corr[qw + r4 + 8];
    size_t ob = ((size_t)(b * SS + q0)) * DD + h * DHH;
    #pragma unroll
    for (int nt = 0; nt < 4; nt++) {
        int col = dw + nt * 8 + tig * 2;
        unsigned hh, ll;
        split2(Oacc[nt][0] * li0, Oacc[nt][1] * li0, hh, ll);
        *(unsigned*)&ctx_hi[ob + (size_t)(qw + r4) * DD + col] = hh;
        *(unsigned*)&ctx_lo[ob + (size_t)(qw + r4) * DD + col] = ll;
        split2(Oacc[nt][2] * li1, Oacc[nt][3] * li1, hh, ll);
        *(unsigned*)&ctx_hi[ob + (size_t)(qw + r4 + 8) * DD + col] = hh;
        *(unsigned*)&ctx_lo[ob + (size_t)(qw + r4 + 8) * DD + col] = ll;
    }
}

// ============================================================================
// launch
// ============================================================================
static float* gsym(const void* sym) {
    void* p = nullptr;
    cudaGetSymbolAddress(&p, sym);
    return (float*)p;
}

extern "C" void kernel_launch(void* const* d_in, const int* in_sizes, int n_in,
                              void* d_out, int out_size)
{
    (void)in_sizes; (void)n_in; (void)out_size;
    const float* q  = (const float*)d_in[0];
    const float* k  = (const float*)d_in[1];
    const float* v  = (const float*)d_in[2];
    const float* Wq = (const float*)d_in[3];
    const float* bq = (const float*)d_in[4];
    const float* Wk = (const float*)d_in[5];
    const float* bk = (const float*)d_in[6];
    const float* Wv = (const float*)d_in[7];
    const float* bv = (const float*)d_in[8];
    const float* Wo = (const float*)d_in[9];
    const float* bo = (const float*)d_in[10];
    float* out = (float*)d_out;

    __nv_bfloat16 *q_hi  = (__nv_bfloat16*)gsym(g_q_hi),  *q_lo  = (__nv_bfloat16*)gsym(g_q_lo);
    __nv_bfloat16 *k_hi  = (__nv_bfloat16*)gsym(g_k_hi),  *k_lo  = (__nv_bfloat16*)gsym(g_k_lo);
    __nv_bfloat16 *v_hi  = (__nv_bfloat16*)gsym(g_v_hi),  *v_lo  = (__nv_bfloat16*)gsym(g_v_lo);
    __nv_bfloat16 *Wq_hi = (__nv_bfloat16*)gsym(g_Wq_hi), *Wq_lo = (__nv_bfloat16*)gsym(g_Wq_lo);
    __nv_bfloat16 *Wk_hi = (__nv_bfloat16*)gsym(g_Wk_hi), *Wk_lo = (__nv_bfloat16*)gsym(g_Wk_lo);
    __nv_bfloat16 *Wv_hi = (__nv_bfloat16*)gsym(g_Wv_hi), *Wv_lo = (__nv_bfloat16*)gsym(g_Wv_lo);
    __nv_bfloat16 *Wo_hi = (__nv_bfloat16*)gsym(g_Wo_hi), *Wo_lo = (__nv_bfloat16*)gsym(g_Wo_lo);
    __nv_bfloat16 *qh_hi = (__nv_bfloat16*)gsym(g_qh_hi), *qh_lo = (__nv_bfloat16*)gsym(g_qh_lo);
    __nv_bfloat16 *kh_hi = (__nv_bfloat16*)gsym(g_kh_hi), *kh_lo = (__nv_bfloat16*)gsym(g_kh_lo);
    __nv_bfloat16 *vh_hi = (__nv_bfloat16*)gsym(g_vh_hi), *vh_lo = (__nv_bfloat16*)gsym(g_vh_lo);
    __nv_bfloat16 *ct_hi = (__nv_bfloat16*)gsym(g_ctx_hi),*ct_lo = (__nv_bfloat16*)gsym(g_ctx_lo);

    cudaFuncSetAttribute(gemm_tc<true>,  cudaFuncAttributeMaxDynamicSharedMemorySize, GEMM_SMEM);
    cudaFuncSetAttribute(gemm_tc<false>, cudaFuncAttributeMaxDynamicSharedMemorySize, GEMM_SMEM);
    cudaFuncSetAttribute(flash_tc,       cudaFuncAttributeMaxDynamicSharedMemorySize, FLASH_SMEM);

    // ---- 0) split inputs + weights ----
    auto spl = [&](const float* x, __nv_bfloat16* hi, __nv_bfloat16* lo, size_t n) {
        split_kernel<<<(unsigned)((n / 4 + 255) / 256), 256>>>(x, hi, lo, (int)n);
    };
    spl(q,  q_hi,  q_lo,  (size_t)MM * DD);
    spl(k,  k_hi,  k_lo,  (size_t)MM * DD);
    spl(v,  v_hi,  v_lo,  (size_t)MM * DD);
    spl(Wq, Wq_hi, Wq_lo, (size_t)DD * DD);
    spl(Wk, Wk_hi, Wk_lo, (size_t)DD * DHH);
    spl(Wv, Wv_hi, Wv_lo, (size_t)DD * DHH);
    spl(Wo, Wo_hi, Wo_lo, (size_t)DD * DD);

    const float qscale = 0.08838834764831845f;   // 1/sqrt(128)

    // ---- 1) Q projection (split out, pre-scaled) ----
    {
        GemmArgs a{q_hi, q_lo, Wq_hi, Wq_lo, bq, nullptr, qh_hi, qh_lo, qscale};
        dim3 grid(DD / 128, MM / 128, 1);
        gemm_tc<true><<<grid, 256, GEMM_SMEM>>>(a, a, MM, DD, DD);
    }
    // ---- 2) K and V projections fused via grid.z ----
    {
        GemmArgs ak{k_hi, k_lo, Wk_hi, Wk_lo, bk, nullptr, kh_hi, kh_lo, 1.0f};
        GemmArgs av{v_hi, v_lo, Wv_hi, Wv_lo, bv, nullptr, vh_hi, vh_lo, 1.0f};
        dim3 grid(DHH / 128, MM / 128, 2);
        gemm_tc<true><<<grid, 256, GEMM_SMEM>>>(ak, av, MM, DHH, DD);
    }
    // ---- 3) fused attention ----
    {
        dim3 grid(SS / 64, HH, BB);
        flash_tc<<<grid, 512, FLASH_SMEM>>>(qh_hi, qh_lo, kh_hi, kh_lo,
                                            vh_hi, vh_lo, ct_hi, ct_lo);
    }
    // ---- 4) output projection (fp32 out) ----
    {
        GemmArgs a{ct_hi, ct_lo, Wo_hi, Wo_lo, bo, out, nullptr, nullptr, 1.0f};
        dim3 grid(DD / 128, MM / 128, 1);
        gemm_tc<false><<<grid, 256, GEMM_SMEM>>>(a, a, MM, DD, DD);
    }
}